// round 10
// baseline (speedup 1.0000x reference)
#include <cuda_runtime.h>
#include <cuda_bf16.h>
#include <cuda_fp16.h>
#include <cstdint>
#include <math.h>

#define SEQ 4096
#define DIM 1024
#define NH  16
#define HD  64

// ---------------------------------------------------------------------------
// Scratch (allocation-free rule: __device__ globals)
// ---------------------------------------------------------------------------
// bf16 split (Q/K path — feeds exp, needs 3-term accuracy)
__device__ __align__(16) __nv_bfloat16 g_xh[SEQ * DIM],  g_xl[SEQ * DIM];
__device__ __align__(16) __nv_bfloat16 g_Qh[SEQ * DIM],  g_Ql[SEQ * DIM];   // pre-scaled 0.125
__device__ __align__(16) __nv_bfloat16 g_Kh[SEQ * DIM],  g_Kl[SEQ * DIM];
__device__ __align__(16) __nv_bfloat16 g_Wqh[DIM * DIM], g_Wql[DIM * DIM];
__device__ __align__(16) __nv_bfloat16 g_Wkh[DIM * DIM], g_Wkl[DIM * DIM];
// fp16 (V / ctx / out path — linear, error dilutes)
__device__ __align__(16) __half g_xfh[SEQ * DIM], g_xfl[SEQ * DIM];         // x fp16 split
__device__ __align__(16) __half g_Wvf[DIM * DIM];                           // Wv fp16 single
__device__ __align__(16) __half g_Wof[DIM * DIM];                           // Wo fp16 single
__device__ __align__(16) __half g_Vth[DIM * SEQ];                           // V transposed fp16 single
__device__ __align__(16) __half g_ch[SEQ * DIM],  g_cl[SEQ * DIM];          // ctx fp16 split

// ---------------------------------------------------------------------------
// PTX helpers (baseline PTX only — compute_103-safe)
// ---------------------------------------------------------------------------
__device__ __forceinline__ uint32_t smem_u32(const void* p) {
    uint32_t a;
    asm("{ .reg .u64 t; cvta.to.shared.u64 t, %1; cvt.u32.u64 %0, t; }"
        : "=r"(a) : "l"(p));
    return a;
}
#define CP_ASYNC16(dst, src) \
    asm volatile("cp.async.ca.shared.global [%0], [%1], 16;" \
                 :: "r"(dst), "l"(src) : "memory")
#define CP_COMMIT()  asm volatile("cp.async.commit_group;" ::: "memory")
#define CP_WAIT1()   asm volatile("cp.async.wait_group 1;" ::: "memory")
#define CP_WAIT0()   asm volatile("cp.async.wait_group 0;" ::: "memory")

__device__ __forceinline__ void mma16816(float* c,
                                         uint32_t a0, uint32_t a1, uint32_t a2, uint32_t a3,
                                         uint32_t b0, uint32_t b1) {
    asm volatile(
        "mma.sync.aligned.m16n8k16.row.col.f32.bf16.bf16.f32 "
        "{%0,%1,%2,%3}, {%4,%5,%6,%7}, {%8,%9}, {%0,%1,%2,%3};"
        : "+f"(c[0]), "+f"(c[1]), "+f"(c[2]), "+f"(c[3])
        : "r"(a0), "r"(a1), "r"(a2), "r"(a3), "r"(b0), "r"(b1));
}
__device__ __forceinline__ void mma16816h(float* c,
                                          uint32_t a0, uint32_t a1, uint32_t a2, uint32_t a3,
                                          uint32_t b0, uint32_t b1) {
    asm volatile(
        "mma.sync.aligned.m16n8k16.row.col.f32.f16.f16.f32 "
        "{%0,%1,%2,%3}, {%4,%5,%6,%7}, {%8,%9}, {%0,%1,%2,%3};"
        : "+f"(c[0]), "+f"(c[1]), "+f"(c[2]), "+f"(c[3])
        : "r"(a0), "r"(a1), "r"(a2), "r"(a3), "r"(b0), "r"(b1));
}

__device__ __forceinline__ void split2(float v0, float v1, uint32_t& hi, uint32_t& lo) {
    __nv_bfloat16 h0 = __float2bfloat16(v0), h1 = __float2bfloat16(v1);
    __nv_bfloat16 l0 = __float2bfloat16(v0 - __bfloat162float(h0));
    __nv_bfloat16 l1 = __float2bfloat16(v1 - __bfloat162float(h1));
    hi = ((uint32_t)__bfloat16_as_ushort(h1) << 16) | __bfloat16_as_ushort(h0);
    lo = ((uint32_t)__bfloat16_as_ushort(l1) << 16) | __bfloat16_as_ushort(l0);
}
__device__ __forceinline__ void split2h(float v0, float v1, uint32_t& hi, uint32_t& lo) {
    __half h0 = __float2half(v0), h1 = __float2half(v1);
    __half l0 = __float2half(v0 - __half2float(h0));
    __half l1 = __float2half(v1 - __half2float(h1));
    hi = ((uint32_t)__half_as_ushort(h1) << 16) | __half_as_ushort(h0);
    lo = ((uint32_t)__half_as_ushort(l1) << 16) | __half_as_ushort(l0);
}
__device__ __forceinline__ uint32_t pack2h(float v0, float v1) {
    return ((uint32_t)__half_as_ushort(__float2half(v1)) << 16) |
           __half_as_ushort(__float2half(v0));
}

// ---------------------------------------------------------------------------
// Converters. sel: 0=x->bf16split 1=Wq 2=Wk (bf16 split)
//                  3=x->f16split  4=Wv->f16 single  5=Wo->f16 single
// ---------------------------------------------------------------------------
__global__ __launch_bounds__(256) void convert_kernel(const float* __restrict__ src,
                                                      int sel, int rows)
{
    int id = blockIdx.x * 256 + threadIdx.x;
    int r = id >> 7;
    if (r >= rows) return;
    int c = (id & 127) << 3;
    size_t off = (size_t)r * DIM + c;

    float4 v0 = *(const float4*)&src[off];
    float4 v1 = *(const float4*)&src[off + 4];
    float v[8] = {v0.x, v0.y, v0.z, v0.w, v1.x, v1.y, v1.z, v1.w};

    if (sel <= 2) {
        __nv_bfloat16* dh = (sel == 0) ? g_xh : ((sel == 1) ? g_Wqh : g_Wkh);
        __nv_bfloat16* dl = (sel == 0) ? g_xl : ((sel == 1) ? g_Wql : g_Wkl);
        union { uint4 u; __nv_bfloat16 b[8]; } H, L;
#pragma unroll
        for (int i = 0; i < 8; i++) {
            __nv_bfloat16 h = __float2bfloat16(v[i]);
            H.b[i] = h;
            L.b[i] = __float2bfloat16(v[i] - __bfloat162float(h));
        }
        *(uint4*)&dh[off] = H.u;
        *(uint4*)&dl[off] = L.u;
    } else if (sel == 3) {
        union { uint4 u; __half b[8]; } H, L;
#pragma unroll
        for (int i = 0; i < 8; i++) {
            __half h = __float2half(v[i]);
            H.b[i] = h;
            L.b[i] = __float2half(v[i] - __half2float(h));
        }
        *(uint4*)&g_xfh[off] = H.u;
        *(uint4*)&g_xfl[off] = L.u;
    } else {
        __half* d = (sel == 4) ? g_Wvf : g_Wof;
        union { uint4 u; __half b[8]; } H;
#pragma unroll
        for (int i = 0; i < 8; i++) H.b[i] = __float2half(v[i]);
        *(uint4*)&d[off] = H.u;
    }
}

// ---------------------------------------------------------------------------
// bf16 3-term GEMM (Q/K projections). CTA 128x128, k-chunk 32, double buffer.
// Epilogue: split-bf16 row-major stores with scale.
// ---------------------------------------------------------------------------
#define MAT_BYTES   (128 * 40 * 2)            // 10240
#define STAGE_B4    (4 * MAT_BYTES)           // 40960
#define MM_SMEM_B   (2 * STAGE_B4)            // 81920
#define STAGE_F3    (3 * MAT_BYTES)           // 30720
#define MM_SMEM_F   (2 * STAGE_F3)            // 61440

__global__ __launch_bounds__(256) void mm_qk_kernel()
{
    const __nv_bfloat16* Ah = g_xh; const __nv_bfloat16* Al = g_xl;
    const __nv_bfloat16* Bh = (blockIdx.z == 0) ? g_Wqh : g_Wkh;
    const __nv_bfloat16* Bl = (blockIdx.z == 0) ? g_Wql : g_Wkl;
    __nv_bfloat16* Dh = (blockIdx.z == 0) ? g_Qh : g_Kh;
    __nv_bfloat16* Dl = (blockIdx.z == 0) ? g_Ql : g_Kl;
    const float scale = (blockIdx.z == 0) ? 0.125f : 1.0f;

    extern __shared__ char smem[];
    const uint32_t sb = smem_u32(smem);
    const int tid  = threadIdx.x;
    const int wid  = tid >> 5;
    const int lane = tid & 31;
    const int wm   = wid & 1;
    const int wn   = wid >> 1;
    const int mb   = blockIdx.y;
    const int nb   = blockIdx.x;
    const int r4 = lane >> 2;
    const int kq = (lane & 3) * 2;

    float acc[4][4][4];
#pragma unroll
    for (int fm = 0; fm < 4; fm++)
#pragma unroll
        for (int fn = 0; fn < 4; fn++)
#pragma unroll
            for (int q = 0; q < 4; q++) acc[fm][fn][q] = 0.0f;

    auto load_chunk = [&](int stage, int ch) {
        const uint32_t st = sb + stage * STAGE_B4;
#pragma unroll
        for (int it = 0; it < 2; it++) {
            int i = tid + it * 256;
            int r = i >> 2, sec = i & 3;
            uint32_t d = st + r * 80 + sec * 16;
            size_t ga = (size_t)(mb * 128 + r) * DIM + ch * 32 + sec * 8;
            size_t gb = (size_t)(nb * 128 + r) * DIM + ch * 32 + sec * 8;
            CP_ASYNC16(d,                 Ah + ga);
            CP_ASYNC16(d + MAT_BYTES,     Al + ga);
            CP_ASYNC16(d + 2 * MAT_BYTES, Bh + gb);
            CP_ASYNC16(d + 3 * MAT_BYTES, Bl + gb);
        }
    };

    load_chunk(0, 0);
    CP_COMMIT();

#pragma unroll 1
    for (int ch = 0; ch < 32; ch++) {
        if (ch + 1 < 32) { load_chunk((ch + 1) & 1, ch + 1); CP_COMMIT(); CP_WAIT1(); }
        else             { CP_WAIT0(); }
        __syncthreads();

        const char* stg = smem + (ch & 1) * STAGE_B4;
        const char* aB  = stg + (wm * 64) * 80;
        const char* bB  = stg + 2 * MAT_BYTES + (wn * 32) * 80;

#pragma unroll
        for (int ks = 0; ks < 2; ks++) {
            const int kb = (ks * 16 + kq) * 2;
            uint32_t bh[4][2], bl[4][2];
#pragma unroll
            for (int fn = 0; fn < 4; fn++) {
                const char* p = bB + (fn * 8 + r4) * 80 + kb;
                bh[fn][0] = *(const uint32_t*)p;
                bh[fn][1] = *(const uint32_t*)(p + 16);
                bl[fn][0] = *(const uint32_t*)(p + MAT_BYTES);
                bl[fn][1] = *(const uint32_t*)(p + MAT_BYTES + 16);
            }
#pragma unroll
            for (int fm = 0; fm < 4; fm++) {
                const char* p = aB + (fm * 16 + r4) * 80 + kb;
                uint32_t ah0 = *(const uint32_t*)p;
                uint32_t ah1 = *(const uint32_t*)(p + 8 * 80);
                uint32_t ah2 = *(const uint32_t*)(p + 16);
                uint32_t ah3 = *(const uint32_t*)(p + 8 * 80 + 16);
                uint32_t al0 = *(const uint32_t*)(p + MAT_BYTES);
                uint32_t al1 = *(const uint32_t*)(p + MAT_BYTES + 8 * 80);
                uint32_t al2 = *(const uint32_t*)(p + MAT_BYTES + 16);
                uint32_t al3 = *(const uint32_t*)(p + MAT_BYTES + 8 * 80 + 16);
#pragma unroll
                for (int fn = 0; fn < 4; fn++) {
                    mma16816(acc[fm][fn], ah0, ah1, ah2, ah3, bh[fn][0], bh[fn][1]);
                    mma16816(acc[fm][fn], ah0, ah1, ah2, ah3, bl[fn][0], bl[fn][1]);
                    mma16816(acc[fm][fn], al0, al1, al2, al3, bh[fn][0], bh[fn][1]);
                }
            }
        }
        __syncthreads();
    }

#pragma unroll
    for (int fm = 0; fm < 4; fm++) {
        const int row = mb * 128 + wm * 64 + fm * 16 + r4;
#pragma unroll
        for (int fn = 0; fn < 4; fn++) {
            const int col = nb * 128 + wn * 32 + fn * 8 + kq;
            uint32_t hi, lo;
            split2(acc[fm][fn][0] * scale, acc[fm][fn][1] * scale, hi, lo);
            *(uint32_t*)&Dh[(size_t)row * DIM + col] = hi;
            *(uint32_t*)&Dl[(size_t)row * DIM + col] = lo;
            split2(acc[fm][fn][2] * scale, acc[fm][fn][3] * scale, hi, lo);
            *(uint32_t*)&Dh[(size_t)(row + 8) * DIM + col] = hi;
            *(uint32_t*)&Dl[(size_t)(row + 8) * DIM + col] = lo;
        }
    }
}

// ---------------------------------------------------------------------------
// fp16 2-term GEMM (A fp16 split x B fp16 single).
// mode 0: fp32 + bias (out). mode 1: transposed fp16 single store (V).
// ---------------------------------------------------------------------------
__device__ __forceinline__ void mm_tile_f16(const __half* __restrict__ Ah,
                                            const __half* __restrict__ Al,
                                            const __half* __restrict__ B,
                                            float* __restrict__ Cf,
                                            const float* __restrict__ bias,
                                            __half* __restrict__ Dt,
                                            int mode)
{
    extern __shared__ char smem[];
    const uint32_t sb = smem_u32(smem);
    const int tid  = threadIdx.x;
    const int wid  = tid >> 5;
    const int lane = tid & 31;
    const int wm   = wid & 1;
    const int wn   = wid >> 1;
    const int mb   = blockIdx.y;
    const int nb   = blockIdx.x;
    const int r4 = lane >> 2;
    const int kq = (lane & 3) * 2;

    float acc[4][4][4];
#pragma unroll
    for (int fm = 0; fm < 4; fm++)
#pragma unroll
        for (int fn = 0; fn < 4; fn++)
#pragma unroll
            for (int q = 0; q < 4; q++) acc[fm][fn][q] = 0.0f;

    auto load_chunk = [&](int stage, int ch) {
        const uint32_t st = sb + stage * STAGE_F3;
#pragma unroll
        for (int it = 0; it < 2; it++) {
            int i = tid + it * 256;
            int r = i >> 2, sec = i & 3;
            uint32_t d = st + r * 80 + sec * 16;
            size_t ga = (size_t)(mb * 128 + r) * DIM + ch * 32 + sec * 8;
            size_t gb = (size_t)(nb * 128 + r) * DIM + ch * 32 + sec * 8;
            CP_ASYNC16(d,                 Ah + ga);
            CP_ASYNC16(d + MAT_BYTES,     Al + ga);
            CP_ASYNC16(d + 2 * MAT_BYTES, B  + gb);
        }
    };

    load_chunk(0, 0);
    CP_COMMIT();

#pragma unroll 1
    for (int ch = 0; ch < 32; ch++) {
        if (ch + 1 < 32) { load_chunk((ch + 1) & 1, ch + 1); CP_COMMIT(); CP_WAIT1(); }
        else             { CP_WAIT0(); }
        __syncthreads();

        const char* stg = smem + (ch & 1) * STAGE_F3;
        const char* aB  = stg + (wm * 64) * 80;
        const char* bB  = stg + 2 * MAT_BYTES + (wn * 32) * 80;

#pragma unroll
        for (int ks = 0; ks < 2; ks++) {
            const int kb = (ks * 16 + kq) * 2;
            uint32_t bh[4][2];
#pragma unroll
            for (int fn = 0; fn < 4; fn++) {
                const char* p = bB + (fn * 8 + r4) * 80 + kb;
                bh[fn][0] = *(const uint32_t*)p;
                bh[fn][1] = *(const uint32_t*)(p + 16);
            }
#pragma unroll
            for (int fm = 0; fm < 4; fm++) {
                const char* p = aB + (fm * 16 + r4) * 80 + kb;
                uint32_t ah0 = *(const uint32_t*)p;
                uint32_t ah1 = *(const uint32_t*)(p + 8 * 80);
                uint32_t ah2 = *(const uint32_t*)(p + 16);
                uint32_t ah3 = *(const uint32_t*)(p + 8 * 80 + 16);
                uint32_t al0 = *(const uint32_t*)(p + MAT_BYTES);
                uint32_t al1 = *(const uint32_t*)(p + MAT_BYTES + 8 * 80);
                uint32_t al2 = *(const uint32_t*)(p + MAT_BYTES + 16);
                uint32_t al3 = *(const uint32_t*)(p + MAT_BYTES + 8 * 80 + 16);
#pragma unroll
                for (int fn = 0; fn < 4; fn++) {
                    mma16816h(acc[fm][fn], ah0, ah1, ah2, ah3, bh[fn][0], bh[fn][1]);
                    mma16816h(acc[fm][fn], al0, al1, al2, al3, bh[fn][0], bh[fn][1]);
                }
            }
        }
        __syncthreads();
    }

#pragma unroll
    for (int fm = 0; fm < 4; fm++) {
        const int row = mb * 128 + wm * 64 + fm * 16 + r4;
#pragma unroll
        for (int fn = 0; fn < 4; fn++) {
            const int col = nb * 128 + wn * 32 + fn * 8 + kq;
            float v0 = acc[fm][fn][0], v1 = acc[fm][fn][1];
            float v2 = acc[fm][fn][2], v3 = acc[fm][fn][3];
            if (mode == 0) {
                float b0 = bias[col], b1 = bias[col + 1];
                *(float2*)&Cf[(size_t)row * DIM + col] = make_float2(v0 + b0, v1 + b1);
                *(float2*)&Cf[(size_t)(row + 8) * DIM + col] = make_float2(v2 + b0, v3 + b1);
            } else {
                Dt[(size_t)col * SEQ + row]           = __float2half(v0);
                Dt[(size_t)(col + 1) * SEQ + row]     = __float2half(v1);
                Dt[(size_t)col * SEQ + row + 8]       = __float2half(v2);
                Dt[(size_t)(col + 1) * SEQ + row + 8] = __float2half(v3);
            }
        }
    }
}

__global__ __launch_bounds__(256) void mm_v_kernel()
{
    mm_tile_f16(g_xfh, g_xfl, g_Wvf, nullptr, nullptr, g_Vth, 1);
}
__global__ __launch_bounds__(256) void mm_out_kernel(const float* __restrict__ bo,
                                                     float* __restrict__ out)
{
    mm_tile_f16(g_ch, g_cl, g_Wof, out, bo, nullptr, 0);
}

// ---------------------------------------------------------------------------
// Flash attention. S = QK^T on bf16 3-term split; PV on single-fp16 P and V.
// Br=Bc=128, 256 threads. K tiles bf16 split (stride 144B), V tile fp16
// single transposed (stride 272B), cp.async double-buffered.
// ---------------------------------------------------------------------------
#define KSTRIDE_B 144
#define VSTRIDE_B 272
#define KBYTES   (128 * KSTRIDE_B)            // 18432
#define VBYTES   (64 * VSTRIDE_B)             // 17408
#define STAGE_A  (2 * KBYTES + VBYTES)        // 54272
#define ATTN_SMEM (2 * STAGE_A)               // 108544

__global__ __launch_bounds__(256, 1) void attn_kernel()
{
    extern __shared__ char smem[];
    const uint32_t sb = smem_u32(smem);
    const int tid  = threadIdx.x;
    const int wid  = tid >> 5;
    const int lane = tid & 31;
    const int r4   = lane >> 2;
    const int kq   = (lane & 3) * 2;
    const int qb   = (gridDim.x - 1) - blockIdx.x;
    const int h    = blockIdx.y;
    const int hc   = h * HD;

    const int R0 = qb * 128 + wid * 16 + r4;
    const int R1 = R0 + 8;

    uint32_t qh[4][4], ql[4][4];
#pragma unroll
    for (int ks = 0; ks < 4; ks++) {
        const size_t k0 = (size_t)hc + ks * 16 + kq;
        qh[ks][0] = *(const uint32_t*)&g_Qh[(size_t)R0 * DIM + k0];
        qh[ks][1] = *(const uint32_t*)&g_Qh[(size_t)R1 * DIM + k0];
        qh[ks][2] = *(const uint32_t*)&g_Qh[(size_t)R0 * DIM + k0 + 8];
        qh[ks][3] = *(const uint32_t*)&g_Qh[(size_t)R1 * DIM + k0 + 8];
        ql[ks][0] = *(const uint32_t*)&g_Ql[(size_t)R0 * DIM + k0];
        ql[ks][1] = *(const uint32_t*)&g_Ql[(size_t)R1 * DIM + k0];
        ql[ks][2] = *(const uint32_t*)&g_Ql[(size_t)R0 * DIM + k0 + 8];
        ql[ks][3] = *(const uint32_t*)&g_Ql[(size_t)R1 * DIM + k0 + 8];
    }

    float o[8][4];
#pragma unroll
    for (int i = 0; i < 8; i++)
#pragma unroll
        for (int j = 0; j < 4; j++) o[i][j] = 0.0f;
    float m0 = -1e30f, m1 = -1e30f, l0 = 0.0f, l1 = 0.0f;

    auto load_stage = [&](int stg, int kb) {
        const uint32_t st = sb + stg * STAGE_A;
#pragma unroll
        for (int it = 0; it < 4; it++) {
            int i = tid + it * 256;
            int r = i >> 3, sec = i & 7;
            uint32_t d = st + r * KSTRIDE_B + sec * 16;
            size_t g = (size_t)(kb * 128 + r) * DIM + hc + sec * 8;
            CP_ASYNC16(d, g_Kh + g);
            CP_ASYNC16(d + KBYTES, g_Kl + g);
        }
        const uint32_t vst = st + 2 * KBYTES;
#pragma unroll
        for (int it = 0; it < 4; it++) {
            int i = tid + it * 256;
            int dd = i >> 4, sec = i & 15;
            uint32_t d = vst + dd * VSTRIDE_B + sec * 16;
            size_t g = (size_t)(hc + dd) * SEQ + kb * 128 + sec * 8;
            CP_ASYNC16(d, g_Vth + g);
        }
    };

    load_stage(0, 0);
    CP_COMMIT();

#pragma unroll 1
    for (int kb = 0; kb <= qb; kb++) {
        if (kb < qb) { load_stage((kb + 1) & 1, kb + 1); CP_COMMIT(); CP_WAIT1(); }
        else         { CP_WAIT0(); }
        __syncthreads();

        const char* kbase = smem + (kb & 1) * STAGE_A;
        const char* vbase = kbase + 2 * KBYTES;

        // S = Q @ K^T (bf16 3-term)
        float s[16][4];
#pragma unroll
        for (int nf = 0; nf < 16; nf++) {
#pragma unroll
            for (int q = 0; q < 4; q++) s[nf][q] = 0.0f;
#pragma unroll
            for (int ks = 0; ks < 4; ks++) {
                const char* p = kbase + (nf * 8 + r4) * KSTRIDE_B + (ks * 16 + kq) * 2;
                uint32_t bh0 = *(const uint32_t*)p;
                uint32_t bh1 = *(const uint32_t*)(p + 16);
                uint32_t bl0 = *(const uint32_t*)(p + KBYTES);
                uint32_t bl1 = *(const uint32_t*)(p + KBYTES + 16);
                mma16816(s[nf], qh[ks][0], qh[ks][1], qh[ks][2], qh[ks][3], bh0, bh1);
                mma16816(s[nf], qh[ks][0], qh[ks][1], qh[ks][2], qh[ks][3], bl0, bl1);
                mma16816(s[nf], ql[ks][0], ql[ks][1], ql[ks][2], ql[ks][3], bh0, bh1);
            }
        }

        if (kb == qb) {
#pragma unroll
            for (int nf = 0; nf < 16; nf++) {
                int C0 = kb * 128 + nf * 8 + kq;
                if (C0 > R0)     s[nf][0] = -1e30f;
                if (C0 + 1 > R0) s[nf][1] = -1e30f;
                if (C0 > R1)     s[nf][2] = -1e30f;
                if (C0 + 1 > R1) s[nf][3] = -1e30f;
            }
        }

        // online softmax
        {
            float mx0 = m0, mx1 = m1;
#pragma unroll
            for (int nf = 0; nf < 16; nf++) {
                mx0 = fmaxf(mx0, fmaxf(s[nf][0], s[nf][1]));
                mx1 = fmaxf(mx1, fmaxf(s[nf][2], s[nf][3]));
            }
            mx0 = fmaxf(mx0, __shfl_xor_sync(0xffffffffu, mx0, 1));
            mx0 = fmaxf(mx0, __shfl_xor_sync(0xffffffffu, mx0, 2));
            mx1 = fmaxf(mx1, __shfl_xor_sync(0xffffffffu, mx1, 1));
            mx1 = fmaxf(mx1, __shfl_xor_sync(0xffffffffu, mx1, 2));
            float fac0 = __expf(m0 - mx0);
            float fac1 = __expf(m1 - mx1);
            m0 = mx0; m1 = mx1;
            float sum0 = 0.f, sum1 = 0.f;
#pragma unroll
            for (int nf = 0; nf < 16; nf++) {
                s[nf][0] = __expf(s[nf][0] - mx0);
                s[nf][1] = __expf(s[nf][1] - mx0);
                s[nf][2] = __expf(s[nf][2] - mx1);
                s[nf][3] = __expf(s[nf][3] - mx1);
                sum0 += s[nf][0] + s[nf][1];
                sum1 += s[nf][2] + s[nf][3];
            }
            sum0 += __shfl_xor_sync(0xffffffffu, sum0, 1);
            sum0 += __shfl_xor_sync(0xffffffffu, sum0, 2);
            sum1 += __shfl_xor_sync(0xffffffffu, sum1, 1);
            sum1 += __shfl_xor_sync(0xffffffffu, sum1, 2);
            l0 = l0 * fac0 + sum0;
            l1 = l1 * fac1 + sum1;
#pragma unroll
            for (int i = 0; i < 8; i++) {
                o[i][0] *= fac0; o[i][1] *= fac0;
                o[i][2] *= fac1; o[i][3] *= fac1;
            }
        }

        // O += P @ V : P single fp16 in registers, V single fp16 in smem
#pragma unroll
        for (int kk = 0; kk < 8; kk++) {
            uint32_t p0 = pack2h(s[2 * kk][0],     s[2 * kk][1]);
            uint32_t p1 = pack2h(s[2 * kk][2],     s[2 * kk][3]);
            uint32_t p2 = pack2h(s[2 * kk + 1][0], s[2 * kk + 1][1]);
            uint32_t p3 = pack2h(s[2 * kk + 1][2], s[2 * kk + 1][3]);
#pragma unroll
            for (int onf = 0; onf < 8; onf++) {
                const char* p = vbase + (onf * 8 + r4) * VSTRIDE_B + (kk * 16 + kq) * 2;
                uint32_t bh0 = *(const uint32_t*)p;
                uint32_t bh1 = *(const uint32_t*)(p + 16);
                mma16816h(o[onf], p0, p1, p2, p3, bh0, bh1);
            }
        }
        __syncthreads();
    }

    // epilogue: normalize, split to fp16 pair, store ctx
    const float i0 = 1.0f / l0;
    const float i1 = 1.0f / l1;
#pragma unroll
    for (int onf = 0; onf < 8; onf++) {
        uint32_t hi, lo;
        const size_t c0 = (size_t)hc + onf * 8 + kq;
        split2h(o[onf][0] * i0, o[onf][1] * i0, hi, lo);
        *(uint32_t*)&g_ch[(size_t)R0 * DIM + c0] = hi;
        *(uint32_t*)&g_cl[(size_t)R0 * DIM + c0] = lo;
        split2h(o[onf][2] * i1, o[onf][3] * i1, hi, lo);
        *(uint32_t*)&g_ch[(size_t)R1 * DIM + c0] = hi;
        *(uint32_t*)&g_cl[(size_t)R1 * DIM + c0] = lo;
    }
}

extern "C" void kernel_launch(void* const* d_in, const int* in_sizes, int n_in,
                              void* d_out, int out_size)
{
    (void)in_sizes; (void)n_in; (void)out_size;
    const float* x  = (const float*)d_in[0];
    const float* Wq = (const float*)d_in[1];
    const float* Wk = (const float*)d_in[2];
    const float* Wv = (const float*)d_in[3];
    const float* Wo = (const float*)d_in[4];
    const float* bo = (const float*)d_in[5];
    float* out = (float*)d_out;

    static bool attr_set = false;
    if (!attr_set) {
        cudaFuncSetAttribute(attn_kernel,
                             cudaFuncAttributeMaxDynamicSharedMemorySize, ATTN_SMEM);
        cudaFuncSetAttribute(mm_qk_kernel,
                             cudaFuncAttributeMaxDynamicSharedMemorySize, MM_SMEM_B);
        cudaFuncSetAttribute(mm_v_kernel,
                             cudaFuncAttributeMaxDynamicSharedMemorySize, MM_SMEM_F);
        cudaFuncSetAttribute(mm_out_kernel,
                             cudaFuncAttributeMaxDynamicSharedMemorySize, MM_SMEM_F);
        attr_set = true;
    }

    // 1) conversions
    convert_kernel<<<SEQ * 128 / 256, 256>>>(x,  0, SEQ);   // x  -> bf16 split
    convert_kernel<<<SEQ * 128 / 256, 256>>>(x,  3, SEQ);   // x  -> fp16 split
    convert_kernel<<<DIM * 128 / 256, 256>>>(Wq, 1, DIM);   // Wq -> bf16 split
    convert_kernel<<<DIM * 128 / 256, 256>>>(Wk, 2, DIM);   // Wk -> bf16 split
    convert_kernel<<<DIM * 128 / 256, 256>>>(Wv, 4, DIM);   // Wv -> fp16 single
    convert_kernel<<<DIM * 128 / 256, 256>>>(Wo, 5, DIM);   // Wo -> fp16 single

    // 2) projections
    {
        dim3 grid(DIM / 128, SEQ / 128, 2);
        mm_qk_kernel<<<grid, 256, MM_SMEM_B>>>();
    }
    {
        dim3 grid(DIM / 128, SEQ / 128, 1);
        mm_v_kernel<<<grid, 256, MM_SMEM_F>>>();
    }
    // 3) causal flash attention
    {
        dim3 grid(SEQ / 128, NH);
        attn_kernel<<<grid, 256, ATTN_SMEM>>>();
    }
    // 4) output projection + bias
    {
        dim3 grid(DIM / 128, SEQ / 128, 1);
        mm_out_kernel<<<grid, 256, MM_SMEM_F>>>(bo, out);
    }
}